// round 13
// baseline (speedup 1.0000x reference)
#include <cuda_runtime.h>
#include <cstdint>

// Problem constants
#define BSZ   65536
#define ISZ   512
#define HSZ   128
#define TT    2
#define ESP   2
#define ECM   4
#define ETOT  6

// Fused matrix: C[24][512].  Row c = t*12 + cc; cc 0..5 = logit cols, 6..11 = fe cols.
// Db[24]: per-column bias (logit: bias-part + bg ; fe: b_e . Wt)
#define NC 24
__device__ __align__(16) float g_C[NC * ISZ];
__device__ float g_Db[NC];

// ---------------------------------------------------------------------------
// helpers
// ---------------------------------------------------------------------------
__device__ __forceinline__ uint32_t smem_u32(const void* p) {
    uint32_t a;
    asm("{ .reg .u64 t; cvta.to.shared.u64 t, %1; cvt.u32.u64 %0, t; }"
        : "=r"(a) : "l"(p));
    return a;
}

#define CP_ASYNC16(sm, g) \
    asm volatile("cp.async.cg.shared.global [%0], [%1], 16;" :: "r"(sm), "l"(g))
#define CP_COMMIT() asm volatile("cp.async.commit_group;" ::: "memory")
#define CP_WAIT1()  asm volatile("cp.async.wait_group 1;" ::: "memory")
#define CP_WAIT0()  asm volatile("cp.async.wait_group 0;" ::: "memory")

// packed fp32x2 FMA (Blackwell): d = a*b + d, elementwise on 2 packed floats
#define FMA2(d, a, b) \
    asm("fma.rn.f32x2 %0, %1, %2, %0;" : "+l"(d) : "l"(a), "l"(b))

__device__ __forceinline__ const float* wsel(const float* Wc, const float* Ws,
                                             int t, int ep) {
    return (ep < ESP) ? (Ws + (size_t)(t * ESP + ep) * ISZ * HSZ)
                      : (Wc + (size_t)(ep - ESP) * ISZ * HSZ);
}
__device__ __forceinline__ const float* bselp(const float* bc, const float* bs,
                                              int t, int ep) {
    return (ep < ESP) ? (bs + (t * ESP + ep) * HSZ) : (bc + (ep - ESP) * HSZ);
}

// ---------------------------------------------------------------------------
// Kernel 1: precompute fused matrix (warp per element).
//   jobs [0, 24*512): C[c][i]     c = job>>9, i = job&511
//   jobs [24*512, 24*512+24): Db[c]
// ---------------------------------------------------------------------------
__global__ void __launch_bounds__(256)
precompute_kernel(const float* __restrict__ Wc, const float* __restrict__ bc,
                  const float* __restrict__ Ws, const float* __restrict__ bs,
                  const float* __restrict__ Wg, const float* __restrict__ bg,
                  const float* __restrict__ Wt)
{
    const int lane = threadIdx.x & 31;
    const int wg   = blockIdx.x * 8 + (threadIdx.x >> 5);

    float s = 0.0f;
    if (wg < NC * ISZ) {
        const int c  = wg >> 9;
        const int i  = wg & 511;
        const int t  = c / 12;
        const int cc = c % 12;
        if (cc < ETOT) {
            #pragma unroll
            for (int ep = 0; ep < ETOT; ep++) {
                const float* W = wsel(Wc, Ws, t, ep);
                #pragma unroll
                for (int h = lane; h < HSZ; h += 32)
                    s += W[(size_t)i * HSZ + h]
                       * Wg[(size_t)t * (ETOT * HSZ * ETOT) + (ep * HSZ + h) * ETOT + cc];
            }
        } else {
            const int e = cc - ETOT;                 // 0..5
            const float* W = wsel(Wc, Ws, t, e);
            #pragma unroll
            for (int h = lane; h < HSZ; h += 32)
                s += W[(size_t)i * HSZ + h] * Wt[t * HSZ + h];
        }
        #pragma unroll
        for (int o = 16; o > 0; o >>= 1) s += __shfl_xor_sync(0xFFFFFFFFu, s, o);
        if (lane == 0) g_C[(size_t)c * ISZ + i] = s;
    } else if (wg < NC * ISZ + NC) {
        const int c  = wg - NC * ISZ;
        const int t  = c / 12;
        const int cc = c % 12;
        if (cc < ETOT) {
            for (int f = lane; f < ETOT * HSZ; f += 32) {
                const int ep = f >> 7, h = f & 127;
                s += bselp(bc, bs, t, ep)[h]
                   * Wg[(size_t)t * (ETOT * HSZ * ETOT) + f * ETOT + cc];
            }
        } else {
            const int e = cc - ETOT;
            for (int h = lane; h < HSZ; h += 32)
                s += bselp(bc, bs, t, e)[h] * Wt[t * HSZ + h];
        }
        #pragma unroll
        for (int o = 16; o > 0; o >>= 1) s += __shfl_xor_sync(0xFFFFFFFFu, s, o);
        if (lane == 0) {
            if (cc < ETOT) s += bg[t * ETOT + cc];
            g_Db[c] = s;
        }
    }
}

// ---------------------------------------------------------------------------
// Kernel 2: main pass — thread per (row, task).
//   Thread (b, t) computes its task's 12 dots of 512, softmax, one store.
//   CTA: 256 threads = 128 rows x 2 tasks.  Grid 512.
// SMEM: C [24][512] f32 @ 0               (49152 B)
//       x [2][128 rows][20 floats] @ 49152 (2 x 10240 B)
//   total 69632 B -> 3 CTAs/SM (24 warps)
// ---------------------------------------------------------------------------
#define NCT      12                   // columns per thread (one task)
#define KCH      16
#define NCHUNK   (ISZ / KCH)          // 32
#define ROWS     128                  // rows per CTA
#define XSTRIDE  20                   // floats per staged row (pad 16 -> 20)
#define XBUF     (ROWS * XSTRIDE * 4) // 10240 B
#define OFF_X    (NC * ISZ * 4)       // 49152
#define SMEM_MAIN (OFF_X + 2 * XBUF)  // 69632

__device__ __forceinline__ void load_chunk(uint32_t xb, const float* x,
                                           int row0, int kc, int tid)
{
    // 128 rows x 16 floats = 512 x 16B ops, 2 per thread
    #pragma unroll
    for (int k = 0; k < 2; k++) {
        const int idx = tid + k * 256;
        const int r   = idx >> 2;
        const int q   = idx & 3;
        CP_ASYNC16(xb + (uint32_t)(r * XSTRIDE + q * 4) * 4,
                   x + (size_t)(row0 + r) * ISZ + kc * KCH + q * 4);
    }
}

__global__ void __launch_bounds__(256, 3)
main_kernel(const float* __restrict__ x, const float* __restrict__ bt,
            float* __restrict__ out)
{
    extern __shared__ __align__(16) char smem[];
    const uint32_t sb   = smem_u32(smem);
    const int tid  = threadIdx.x;
    const int row  = tid & (ROWS - 1);
    const int task = tid >> 7;
    const int row0 = blockIdx.x * ROWS;
    const int b    = row0 + row;

    // stage C (48 KB) + chunk 0 in one cp.async group
    {
        const float4* Cg = (const float4*)g_C;
        #pragma unroll
        for (int k = 0; k < 12; k++) {
            const int idx = tid + k * 256;
            CP_ASYNC16(sb + (uint32_t)idx * 16, Cg + idx);
        }
    }
    load_chunk(sb + OFF_X, x, row0, 0, tid);
    CP_COMMIT();

    uint64_t acc[NCT];
    #pragma unroll
    for (int c = 0; c < NCT; c++) acc[c] = 0ull;

    // this thread's task-half of C: 12 rows starting at row task*12
    const char* cbase = smem + (size_t)task * (NCT * ISZ * 4);

    for (int kc = 0; kc < NCHUNK; kc++) {
        const int buf = kc & 1;
        if (kc + 1 < NCHUNK) {
            load_chunk(sb + OFF_X + (buf ^ 1) * XBUF, x, row0, kc + 1, tid);
            CP_COMMIT();
            CP_WAIT1();
        } else {
            CP_WAIT0();
        }
        __syncthreads();     // chunk kc (and C on kc==0) visible

        // this thread's 16 x-values (8 packed pairs)
        const ulonglong2* xr =
            (const ulonglong2*)(smem + OFF_X + buf * XBUF + row * (XSTRIDE * 4));
        const ulonglong2 x0 = xr[0], x1 = xr[1], x2 = xr[2], x3 = xr[3];

        const char* ck = cbase + kc * (KCH * 4);
        #pragma unroll
        for (int c = 0; c < NCT; c++) {
            const ulonglong2* cp = (const ulonglong2*)(ck + (size_t)c * (ISZ * 4));
            ulonglong2 q0 = cp[0], q1 = cp[1], q2 = cp[2], q3 = cp[3];
            FMA2(acc[c], x0.x, q0.x); FMA2(acc[c], x0.y, q0.y);
            FMA2(acc[c], x1.x, q1.x); FMA2(acc[c], x1.y, q1.y);
            FMA2(acc[c], x2.x, q2.x); FMA2(acc[c], x2.y, q2.y);
            FMA2(acc[c], x3.x, q3.x); FMA2(acc[c], x3.y, q3.y);
        }
        __syncthreads();     // all threads done with buf before it is reloaded
    }

    // tail: fold pairs, add bias, per-thread softmax + combine (12 cols, own task)
    float p[NCT];
    #pragma unroll
    for (int c = 0; c < NCT; c++) {
        const float lo = __uint_as_float((uint32_t)acc[c]);
        const float hi = __uint_as_float((uint32_t)(acc[c] >> 32));
        p[c] = lo + hi + __ldg(&g_Db[task * NCT + c]);
    }

    float m = -1e30f;
    #pragma unroll
    for (int oe = 0; oe < ETOT; oe++) m = fmaxf(m, p[oe]);
    float den = 0.0f, num = 0.0f;
    #pragma unroll
    for (int oe = 0; oe < ETOT; oe++) {
        const float w = __expf(p[oe] - m);
        den += w;
        num += w * p[ETOT + oe];
    }
    out[(size_t)task * BSZ + b] = num / den + __ldg(&bt[task]);
}

// ---------------------------------------------------------------------------
// Launch
// ---------------------------------------------------------------------------
extern "C" void kernel_launch(void* const* d_in, const int* in_sizes, int n_in,
                              void* d_out, int out_size)
{
    (void)in_sizes; (void)n_in; (void)out_size;
    const float* x  = (const float*)d_in[0];
    const float* Wc = (const float*)d_in[1];
    const float* bc = (const float*)d_in[2];
    const float* Ws = (const float*)d_in[3];
    const float* bs = (const float*)d_in[4];
    const float* Wg = (const float*)d_in[5];
    const float* bg = (const float*)d_in[6];
    const float* Wt = (const float*)d_in[7];
    const float* bt = (const float*)d_in[8];
    float* out = (float*)d_out;

    cudaFuncSetAttribute(main_kernel,
                         cudaFuncAttributeMaxDynamicSharedMemorySize, SMEM_MAIN);

    const int njobs = NC * ISZ + NC;                  // 12312 warp-jobs
    precompute_kernel<<<(njobs + 7) / 8, 256>>>(Wc, bc, Ws, bs, Wg, bg, Wt);

    main_kernel<<<BSZ / ROWS, 256, SMEM_MAIN>>>(x, bt, out);
}

// round 14
// speedup vs baseline: 1.2508x; 1.2508x over previous
#include <cuda_runtime.h>
#include <cstdint>

// Problem constants
#define BSZ   65536
#define ISZ   512
#define HSZ   128
#define TT    2
#define ESP   2
#define ECM   4
#define ETOT  6

// Fused matrix: C[24][512].  Row c = t*12 + cc; cc 0..5 = logit cols, 6..11 = fe cols.
// Db[24]: per-column bias (logit: bias-part + bg ; fe: b_e . Wt)
#define NC 24
__device__ __align__(16) float g_C[NC * ISZ];
__device__ float g_Db[NC];

// ---------------------------------------------------------------------------
// helpers
// ---------------------------------------------------------------------------
__device__ __forceinline__ uint32_t smem_u32(const void* p) {
    uint32_t a;
    asm("{ .reg .u64 t; cvta.to.shared.u64 t, %1; cvt.u32.u64 %0, t; }"
        : "=r"(a) : "l"(p));
    return a;
}

#define CP_ASYNC16(sm, g) \
    asm volatile("cp.async.cg.shared.global [%0], [%1], 16;" :: "r"(sm), "l"(g))
#define CP_COMMIT() asm volatile("cp.async.commit_group;" ::: "memory")
#define CP_WAIT1()  asm volatile("cp.async.wait_group 1;" ::: "memory")
#define CP_WAIT0()  asm volatile("cp.async.wait_group 0;" ::: "memory")

// packed fp32x2 FMA (Blackwell): d = a*b + d, elementwise on 2 packed floats
#define FMA2(d, a, b) \
    asm("fma.rn.f32x2 %0, %1, %2, %0;" : "+l"(d) : "l"(a), "l"(b))

__device__ __forceinline__ const float* wsel(const float* Wc, const float* Ws,
                                             int t, int ep) {
    return (ep < ESP) ? (Ws + (size_t)(t * ESP + ep) * ISZ * HSZ)
                      : (Wc + (size_t)(ep - ESP) * ISZ * HSZ);
}
__device__ __forceinline__ const float* bselp(const float* bc, const float* bs,
                                              int t, int ep) {
    return (ep < ESP) ? (bs + (t * ESP + ep) * HSZ) : (bc + (ep - ESP) * HSZ);
}

// ---------------------------------------------------------------------------
// Kernel 1: precompute fused matrix (warp per element).
//   jobs [0, 24*512): C[c][i]     c = job>>9, i = job&511
//   jobs [24*512, 24*512+24): Db[c]
// ---------------------------------------------------------------------------
__global__ void __launch_bounds__(256)
precompute_kernel(const float* __restrict__ Wc, const float* __restrict__ bc,
                  const float* __restrict__ Ws, const float* __restrict__ bs,
                  const float* __restrict__ Wg, const float* __restrict__ bg,
                  const float* __restrict__ Wt)
{
    const int lane = threadIdx.x & 31;
    const int wg   = blockIdx.x * 8 + (threadIdx.x >> 5);

    float s = 0.0f;
    if (wg < NC * ISZ) {
        const int c  = wg >> 9;
        const int i  = wg & 511;
        const int t  = c / 12;
        const int cc = c % 12;
        if (cc < ETOT) {
            #pragma unroll
            for (int ep = 0; ep < ETOT; ep++) {
                const float* W = wsel(Wc, Ws, t, ep);
                #pragma unroll
                for (int h = lane; h < HSZ; h += 32)
                    s += W[(size_t)i * HSZ + h]
                       * Wg[(size_t)t * (ETOT * HSZ * ETOT) + (ep * HSZ + h) * ETOT + cc];
            }
        } else {
            const int e = cc - ETOT;                 // 0..5
            const float* W = wsel(Wc, Ws, t, e);
            #pragma unroll
            for (int h = lane; h < HSZ; h += 32)
                s += W[(size_t)i * HSZ + h] * Wt[t * HSZ + h];
        }
        #pragma unroll
        for (int o = 16; o > 0; o >>= 1) s += __shfl_xor_sync(0xFFFFFFFFu, s, o);
        if (lane == 0) g_C[(size_t)c * ISZ + i] = s;
    } else if (wg < NC * ISZ + NC) {
        const int c  = wg - NC * ISZ;
        const int t  = c / 12;
        const int cc = c % 12;
        if (cc < ETOT) {
            for (int f = lane; f < ETOT * HSZ; f += 32) {
                const int ep = f >> 7, h = f & 127;
                s += bselp(bc, bs, t, ep)[h]
                   * Wg[(size_t)t * (ETOT * HSZ * ETOT) + f * ETOT + cc];
            }
        } else {
            const int e = cc - ETOT;
            for (int h = lane; h < HSZ; h += 32)
                s += bselp(bc, bs, t, e)[h] * Wt[t * HSZ + h];
        }
        #pragma unroll
        for (int o = 16; o > 0; o >>= 1) s += __shfl_xor_sync(0xFFFFFFFFu, s, o);
        if (lane == 0) {
            if (cc < ETOT) s += bg[t * ETOT + cc];
            g_Db[c] = s;
        }
    }
}

// ---------------------------------------------------------------------------
// Kernel 2: main pass — thread per (row-pair, task).
//   Thread (p, t) computes rows b0 = blk*256+p and b1 = b0+128 for task t:
//   12 dots of 512 each, C fragments reused across both rows (halves LDS/FLOP).
//   CTA: 256 threads = 128 pairs x 2 tasks -> 256 rows.  Grid 256 (1 wave).
// SMEM: C [24][512] f32 @ 0                (49152 B)
//       x [2][256 rows][20 floats] @ 49152 (2 x 20480 B)
//   total 90112 B -> 2 CTAs/SM (16 warps)
// ---------------------------------------------------------------------------
#define NCT      12                   // columns per thread (one task)
#define KCH      16
#define NCHUNK   (ISZ / KCH)          // 32
#define ROWS     256                  // rows per CTA
#define XSTRIDE  20                   // floats per staged row (pad 16 -> 20)
#define XBUF     (ROWS * XSTRIDE * 4) // 20480 B
#define OFF_X    (NC * ISZ * 4)       // 49152
#define SMEM_MAIN (OFF_X + 2 * XBUF)  // 90112

__device__ __forceinline__ void load_chunk(uint32_t xb, const float* x,
                                           int row0, int kc, int tid)
{
    // 256 rows x 16 floats = 1024 x 16B ops, 4 per thread
    #pragma unroll
    for (int k = 0; k < 4; k++) {
        const int idx = tid + k * 256;
        const int r   = idx >> 2;
        const int q   = idx & 3;
        CP_ASYNC16(xb + (uint32_t)(r * XSTRIDE + q * 4) * 4,
                   x + (size_t)(row0 + r) * ISZ + kc * KCH + q * 4);
    }
}

__global__ void __launch_bounds__(256, 2)
main_kernel(const float* __restrict__ x, const float* __restrict__ bt,
            float* __restrict__ out)
{
    extern __shared__ __align__(16) char smem[];
    const uint32_t sb   = smem_u32(smem);
    const int tid  = threadIdx.x;
    const int p    = tid & 127;          // row-pair index
    const int task = tid >> 7;
    const int row0 = blockIdx.x * ROWS;
    const int b0   = row0 + p;           // rows p and p+128 of this tile

    // stage C (48 KB) + chunk 0 in one cp.async group
    {
        const float4* Cg = (const float4*)g_C;
        #pragma unroll
        for (int k = 0; k < 12; k++) {
            const int idx = tid + k * 256;
            CP_ASYNC16(sb + (uint32_t)idx * 16, Cg + idx);
        }
    }
    load_chunk(sb + OFF_X, x, row0, 0, tid);
    CP_COMMIT();

    uint64_t acc0[NCT], acc1[NCT];
    #pragma unroll
    for (int c = 0; c < NCT; c++) { acc0[c] = 0ull; acc1[c] = 0ull; }

    // this thread's task-half of C: 12 rows starting at row task*12
    const char* cbase = smem + (size_t)task * (NCT * ISZ * 4);

    for (int kc = 0; kc < NCHUNK; kc++) {
        const int buf = kc & 1;
        if (kc + 1 < NCHUNK) {
            load_chunk(sb + OFF_X + (buf ^ 1) * XBUF, x, row0, kc + 1, tid);
            CP_COMMIT();
            CP_WAIT1();
        } else {
            CP_WAIT0();
        }
        __syncthreads();     // chunk kc (and C on kc==0) visible

        // 16 x-values for each of this thread's two rows (8 packed pairs each)
        const char* xrb = smem + OFF_X + buf * XBUF;
        const ulonglong2* xr0 = (const ulonglong2*)(xrb + p * (XSTRIDE * 4));
        const ulonglong2* xr1 = (const ulonglong2*)(xrb + (p + 128) * (XSTRIDE * 4));
        const ulonglong2 a0 = xr0[0], a1 = xr0[1], a2 = xr0[2], a3 = xr0[3];
        const ulonglong2 b1v = xr1[0], b2v = xr1[1], b3v = xr1[2], b4v = xr1[3];

        const char* ck = cbase + kc * (KCH * 4);
        #pragma unroll
        for (int c = 0; c < NCT; c++) {
            const ulonglong2* cp = (const ulonglong2*)(ck + (size_t)c * (ISZ * 4));
            ulonglong2 q0 = cp[0], q1 = cp[1], q2 = cp[2], q3 = cp[3];
            // row 0
            FMA2(acc0[c], a0.x, q0.x); FMA2(acc0[c], a0.y, q0.y);
            FMA2(acc0[c], a1.x, q1.x); FMA2(acc0[c], a1.y, q1.y);
            FMA2(acc0[c], a2.x, q2.x); FMA2(acc0[c], a2.y, q2.y);
            FMA2(acc0[c], a3.x, q3.x); FMA2(acc0[c], a3.y, q3.y);
            // row 1 (same C fragments)
            FMA2(acc1[c], b1v.x, q0.x); FMA2(acc1[c], b1v.y, q0.y);
            FMA2(acc1[c], b2v.x, q1.x); FMA2(acc1[c], b2v.y, q1.y);
            FMA2(acc1[c], b3v.x, q2.x); FMA2(acc1[c], b3v.y, q2.y);
            FMA2(acc1[c], b4v.x, q3.x); FMA2(acc1[c], b4v.y, q3.y);
        }
        __syncthreads();     // all threads done with buf before it is reloaded
    }

    // tail: fold pairs, add bias, per-thread softmax + combine (own task)
    const float btv = __ldg(&bt[task]);
    #pragma unroll
    for (int r = 0; r < 2; r++) {
        const uint64_t* acc = r ? acc1 : acc0;
        float pv[NCT];
        #pragma unroll
        for (int c = 0; c < NCT; c++) {
            const float lo = __uint_as_float((uint32_t)acc[c]);
            const float hi = __uint_as_float((uint32_t)(acc[c] >> 32));
            pv[c] = lo + hi + __ldg(&g_Db[task * NCT + c]);
        }
        float m = -1e30f;
        #pragma unroll
        for (int oe = 0; oe < ETOT; oe++) m = fmaxf(m, pv[oe]);
        float den = 0.0f, num = 0.0f;
        #pragma unroll
        for (int oe = 0; oe < ETOT; oe++) {
            const float w = __expf(pv[oe] - m);
            den += w;
            num += w * pv[ETOT + oe];
        }
        out[(size_t)task * BSZ + b0 + r * 128] = num / den + btv;
    }
}

// ---------------------------------------------------------------------------
// Launch
// ---------------------------------------------------------------------------
extern "C" void kernel_launch(void* const* d_in, const int* in_sizes, int n_in,
                              void* d_out, int out_size)
{
    (void)in_sizes; (void)n_in; (void)out_size;
    const float* x  = (const float*)d_in[0];
    const float* Wc = (const float*)d_in[1];
    const float* bc = (const float*)d_in[2];
    const float* Ws = (const float*)d_in[3];
    const float* bs = (const float*)d_in[4];
    const float* Wg = (const float*)d_in[5];
    const float* bg = (const float*)d_in[6];
    const float* Wt = (const float*)d_in[7];
    const float* bt = (const float*)d_in[8];
    float* out = (float*)d_out;

    cudaFuncSetAttribute(main_kernel,
                         cudaFuncAttributeMaxDynamicSharedMemorySize, SMEM_MAIN);

    const int njobs = NC * ISZ + NC;                  // 12312 warp-jobs
    precompute_kernel<<<(njobs + 7) / 8, 256>>>(Wc, bc, Ws, bs, Wg, bg, Wt);

    main_kernel<<<BSZ / ROWS, 256, SMEM_MAIN>>>(x, bt, out);
}